// round 2
// baseline (speedup 1.0000x reference)
#include <cuda_runtime.h>
#include <math.h>

#define L_SEQ 8192
#define NB 2
#define NH 8
#define PD 32
#define DIM 256
#define M_ROWS (NB * L_SEQ)      // 16384
#define NHB (NB * NH)            // 16
#define CL 64                    // chunk length for scan
#define NCHUNK (L_SEQ / CL)      // 128

// ---------------- scratch (device globals; no allocations allowed) ----------
__device__ float g_pq[(size_t)NHB * L_SEQ * PD];      // phi(Y Wq^T), (nh,l,d)
__device__ float g_pk[(size_t)NHB * L_SEQ * PD];      // phi(X Wk^T)
__device__ float g_v [(size_t)NHB * L_SEQ * PD];      // X Wv^T
__device__ float g_numloc[(size_t)NHB * L_SEQ * PD];  // local inclusive prefix (num)
__device__ float g_denloc[(size_t)NHB * L_SEQ * PD];  // local inclusive prefix (den)
__device__ float g_tot  [NHB * NCHUNK * 2 * PD];      // chunk totals (num|den)
__device__ float g_carry[NHB * NCHUNK * 2 * PD];      // exclusive carries

// ---------------- Kernel 1: projections -------------------------------------
// out[m][j] = sum_k A[m][k] * W[j][k]; stored to (n,h,l,d) layout, phi applied
// for z in {0,1}.
__global__ __launch_bounds__(256) void proj_kernel(
    const float* __restrict__ Y, const float* __restrict__ X,
    const float* __restrict__ Wq, const float* __restrict__ Wk,
    const float* __restrict__ Wv) {
    const int z = blockIdx.z;
    const float* __restrict__ A = (z == 0) ? Y : X;
    const float* __restrict__ W = (z == 0) ? Wq : ((z == 1) ? Wk : Wv);
    float* __restrict__ O = (z == 0) ? g_pq : ((z == 1) ? g_pk : g_v);

    const int rowStart = blockIdx.x * 64;
    const int colStart = blockIdx.y * 64;

    __shared__ float As[16][64];
    __shared__ float Bs[16][64];

    const int tid = threadIdx.x;
    const int ty = tid >> 4;    // 0..15
    const int tx = tid & 15;    // 0..15
    const int lr = tid >> 2;    // 0..63, load row
    const int lk = (tid & 3) * 4;

    float acc[4][4];
    #pragma unroll
    for (int i = 0; i < 4; i++)
        #pragma unroll
        for (int j = 0; j < 4; j++) acc[i][j] = 0.f;

    for (int kt = 0; kt < 256; kt += 16) {
        float4 a = *reinterpret_cast<const float4*>(&A[(size_t)(rowStart + lr) * 256 + kt + lk]);
        float4 b = *reinterpret_cast<const float4*>(&W[(size_t)(colStart + lr) * 256 + kt + lk]);
        As[lk + 0][lr] = a.x; As[lk + 1][lr] = a.y; As[lk + 2][lr] = a.z; As[lk + 3][lr] = a.w;
        Bs[lk + 0][lr] = b.x; Bs[lk + 1][lr] = b.y; Bs[lk + 2][lr] = b.z; Bs[lk + 3][lr] = b.w;
        __syncthreads();
        #pragma unroll
        for (int kk = 0; kk < 16; kk++) {
            float4 ra = *reinterpret_cast<float4*>(&As[kk][ty * 4]);
            float4 rb = *reinterpret_cast<float4*>(&Bs[kk][tx * 4]);
            float av[4] = {ra.x, ra.y, ra.z, ra.w};
            float bv[4] = {rb.x, rb.y, rb.z, rb.w};
            #pragma unroll
            for (int i = 0; i < 4; i++)
                #pragma unroll
                for (int j = 0; j < 4; j++) acc[i][j] += av[i] * bv[j];
        }
        __syncthreads();
    }

    // epilogue: phi for z<2; write to (n,h,l,d)
    #pragma unroll
    for (int i = 0; i < 4; i++) {
        const int m = rowStart + ty * 4 + i;
        const int n = m >> 13;
        const int l = m & (L_SEQ - 1);
        const int jbase = colStart + tx * 4;          // 4 consecutive cols, same head
        const int h = jbase >> 5;
        const int d = jbase & 31;
        float4 o;
        float* p = &((float*)&o)[0];
        #pragma unroll
        for (int j = 0; j < 4; j++) {
            float val = acc[i][j];
            if (z < 2) val = (val > 0.f) ? (val + 1.f) : expf(val);
            p[j] = val;
        }
        size_t off = (((size_t)(n * NH + h) * L_SEQ) + l) * PD + d;
        *reinterpret_cast<float4*>(&O[off]) = o;
    }
}

// ---------------- Kernel 2: per-chunk local scan -----------------------------
__global__ __launch_bounds__(128) void scan_kernel() {
    const int nh = blockIdx.x;         // 0..15
    const int ch = blockIdx.y;         // 0..NCHUNK-1
    const int s = ch * CL;
    const int tid = threadIdx.x;

    __shared__ float spq[(CL + 1) * PD];
    __shared__ float spk[CL * PD];
    __shared__ float sv [CL * PD];
    __shared__ float sc [CL];
    __shared__ float scp[CL];

    const float* __restrict__ pq = g_pq + (size_t)nh * L_SEQ * PD;
    const float* __restrict__ pk = g_pk + (size_t)nh * L_SEQ * PD;
    const float* __restrict__ v  = g_v  + (size_t)nh * L_SEQ * PD;

    // pq rows [s-1, s+CL)
    for (int i = tid; i < (CL + 1) * PD; i += 128) {
        int l = s - 1 + (i >> 5);
        spq[i] = (l >= 0) ? pq[(size_t)l * PD + (i & 31)] : 0.f;
    }
    for (int i = tid; i < CL * PD; i += 128) {
        spk[i] = pk[(size_t)s * PD + i];
        sv[i]  = v [(size_t)s * PD + i];
    }
    __syncthreads();

    // per-position coefficients
    if (tid < CL) {
        float c = 0.f, cp = 0.f;
        #pragma unroll
        for (int d = 0; d < PD; d++) {
            float dq = spq[(tid + 1) * PD + d] - spq[tid * PD + d];
            c  += dq * sv[tid * PD + d];
            cp += dq;
        }
        sc[tid] = c;
        scp[tid] = cp;
    }
    __syncthreads();

    // serial local prefix scan: lanes 0..31 -> num, 32..63 -> den
    if (tid < 64) {
        const int d = tid & 31;
        const bool isden = tid >= 32;
        const float* coef = isden ? scp : sc;
        float* ob = (isden ? g_denloc : g_numloc) + (size_t)nh * L_SEQ * PD + (size_t)s * PD + d;
        float acc = 0.f;
        #pragma unroll 4
        for (int m = 0; m < CL; m++) {
            acc += coef[m] * spk[m * PD + d];
            ob[(size_t)m * PD] = acc;
        }
        g_tot[(nh * NCHUNK + ch) * 64 + tid] = acc;
    }
}

// ---------------- Kernel 3: carries (exclusive scan over chunks) -------------
__global__ __launch_bounds__(64) void carry_kernel() {
    const int nh = blockIdx.x;     // 0..15
    const int slot = threadIdx.x;  // 0..63
    float acc = 0.f;
    for (int ch = 0; ch < NCHUNK; ch++) {
        const int idx = (nh * NCHUNK + ch) * 64 + slot;
        g_carry[idx] = acc;
        acc += g_tot[idx];
    }
}

// ---------------- Kernel 4: finalize -----------------------------------------
__global__ __launch_bounds__(256) void final_kernel(float* __restrict__ out) {
    const size_t idx = (size_t)blockIdx.x * 256 + threadIdx.x;  // over nh,l,d
    const int d = (int)(idx & 31);
    const size_t rest = idx >> 5;
    const int l = (int)(rest & (L_SEQ - 1));
    const int nh = (int)(rest >> 13);
    const int ch = l / CL;

    const float cn = g_carry[(nh * NCHUNK + ch) * 64 + d];
    const float cd = g_carry[(nh * NCHUNK + ch) * 64 + 32 + d];
    const float num = g_numloc[idx] + cn;
    const float den = g_denloc[idx] + cd;

    const int n = nh >> 3;
    const int h = nh & 7;
    out[((size_t)n * L_SEQ + l) * DIM + h * PD + d] = num / den;
}

// ---------------- launch ------------------------------------------------------
extern "C" void kernel_launch(void* const* d_in, const int* in_sizes, int n_in,
                              void* d_out, int out_size) {
    const float* Y  = (const float*)d_in[0];
    const float* X  = (const float*)d_in[1];
    const float* Wq = (const float*)d_in[2];
    const float* Wk = (const float*)d_in[3];
    const float* Wv = (const float*)d_in[4];
    // d_in[5] = mask; always 1 (causal) per problem setup
    float* out = (float*)d_out;

    dim3 pg(M_ROWS / 64, DIM / 64, 3);
    proj_kernel<<<pg, 256>>>(Y, X, Wq, Wk, Wv);

    dim3 sg(NHB, NCHUNK);
    scan_kernel<<<sg, 128>>>();

    carry_kernel<<<NHB, 64>>>();

    final_kernel<<<(size_t)NHB * L_SEQ * PD / 256, 256>>>(out);
}

// round 5
// speedup vs baseline: 1.9572x; 1.9572x over previous
#include <cuda_runtime.h>
#include <math.h>
#include <stdint.h>

#define L_SEQ 8192
#define NB 2
#define NH 8
#define PD 32
#define DIM 256
#define M_ROWS (NB * L_SEQ)      // 16384
#define NHB (NB * NH)            // 16
#define CL 64                    // chunk length for scan
#define NCHUNK (L_SEQ / CL)      // 128

// ---------------- scratch (device globals; no allocations allowed) ----------
__device__ float g_pq[(size_t)NHB * L_SEQ * PD];      // phi(Y Wq^T), (nh,l,d)
__device__ float g_pk[(size_t)NHB * L_SEQ * PD];      // phi(X Wk^T)
__device__ float g_v [(size_t)NHB * L_SEQ * PD];      // X Wv^T
__device__ float g_numloc[(size_t)NHB * L_SEQ * PD];  // local inclusive prefix (num)
__device__ float g_denloc[(size_t)NHB * L_SEQ * PD];  // local inclusive prefix (den)
__device__ float g_tot  [NHB * NCHUNK * 2 * PD];      // chunk totals (num|den)
__device__ float g_carry[NHB * NCHUNK * 2 * PD];      // exclusive carries

// ---------------- helpers -----------------------------------------------------
__device__ __forceinline__ float to_tf32(float x) {
    asm("cvt.rna.tf32.f32 %0, %1;" : "=f"(x) : "f"(x));
    return x;
}

__device__ __forceinline__ void mma_tf32(float c[4],
                                         uint32_t a0, uint32_t a1, uint32_t a2, uint32_t a3,
                                         uint32_t b0, uint32_t b1) {
    asm volatile(
        "mma.sync.aligned.m16n8k8.row.col.f32.tf32.tf32.f32 "
        "{%0,%1,%2,%3}, {%4,%5,%6,%7}, {%8,%9}, {%0,%1,%2,%3};"
        : "+f"(c[0]), "+f"(c[1]), "+f"(c[2]), "+f"(c[3])
        : "r"(a0), "r"(a1), "r"(a2), "r"(a3), "r"(b0), "r"(b1));
}

// ---------------- Kernel 1: projections via TF32 mma.sync ---------------------
// C[m][j] = sum_k A[m][k] * W[j][k]; phi applied for z<2; stored (n,h,l,d).
// Block tile 128(M) x 64(N), 8 warps (4x2), warp tile 32x32, K-tile 32.
#define SAS 36   // smem row stride (floats): banks = 4g+t, conflict-free
__global__ __launch_bounds__(256) void proj_kernel(
    const float* __restrict__ Y, const float* __restrict__ X,
    const float* __restrict__ Wq, const float* __restrict__ Wk,
    const float* __restrict__ Wv) {
    const int z = blockIdx.z;
    const float* __restrict__ A = (z == 0) ? Y : X;
    const float* __restrict__ W = (z == 0) ? Wq : ((z == 1) ? Wk : Wv);
    float* __restrict__ O = (z == 0) ? g_pq : ((z == 1) ? g_pk : g_v);

    const int rowStart = blockIdx.x * 128;
    const int colStart = blockIdx.y * 64;

    __shared__ float As[128 * SAS];   // [row][k] k-tile of A
    __shared__ float Bs[64 * SAS];    // [n][k]  k-tile of W (direct copy)

    const int tid = threadIdx.x;
    const int lane = tid & 31;
    const int wid = tid >> 5;
    const int wm = wid & 3;           // warp row 0..3
    const int wn = wid >> 2;          // warp col 0..1
    const int g = lane >> 2;          // 0..7
    const int t = lane & 3;           // 0..3

    float acc[2][4][4];
    #pragma unroll
    for (int mt = 0; mt < 2; mt++)
        #pragma unroll
        for (int nt = 0; nt < 4; nt++)
            #pragma unroll
            for (int i = 0; i < 4; i++) acc[mt][nt][i] = 0.f;

    for (int kt = 0; kt < 256; kt += 32) {
        // --- stage A tile: 128 x 32 = 1024 float4, 4 per thread
        #pragma unroll
        for (int i = 0; i < 4; i++) {
            const int idx = tid + 256 * i;          // float4 index
            const int r = idx >> 3;                 // 8 float4 per row
            const int c4 = (idx & 7) * 4;
            float4 a = *reinterpret_cast<const float4*>(
                &A[(size_t)(rowStart + r) * 256 + kt + c4]);
            float* p = &As[r * SAS + c4];
            p[0] = to_tf32(a.x); p[1] = to_tf32(a.y);
            p[2] = to_tf32(a.z); p[3] = to_tf32(a.w);
        }
        // --- stage B tile: 64 x 32 = 512 float4, 2 per thread
        #pragma unroll
        for (int i = 0; i < 2; i++) {
            const int idx = tid + 256 * i;
            const int r = idx >> 3;
            const int c4 = (idx & 7) * 4;
            float4 b = *reinterpret_cast<const float4*>(
                &W[(size_t)(colStart + r) * 256 + kt + c4]);
            float* p = &Bs[r * SAS + c4];
            p[0] = to_tf32(b.x); p[1] = to_tf32(b.y);
            p[2] = to_tf32(b.z); p[3] = to_tf32(b.w);
        }
        __syncthreads();

        #pragma unroll
        for (int k8 = 0; k8 < 4; k8++) {
            const int k0 = k8 * 8;
            uint32_t a[2][4];
            #pragma unroll
            for (int mt = 0; mt < 2; mt++) {
                const int r = wm * 32 + mt * 16 + g;
                a[mt][0] = __float_as_uint(As[r * SAS + k0 + t]);
                a[mt][1] = __float_as_uint(As[(r + 8) * SAS + k0 + t]);
                a[mt][2] = __float_as_uint(As[r * SAS + k0 + t + 4]);
                a[mt][3] = __float_as_uint(As[(r + 8) * SAS + k0 + t + 4]);
            }
            uint32_t b[4][2];
            #pragma unroll
            for (int nt = 0; nt < 4; nt++) {
                const int nn = wn * 32 + nt * 8 + g;
                b[nt][0] = __float_as_uint(Bs[nn * SAS + k0 + t]);
                b[nt][1] = __float_as_uint(Bs[nn * SAS + k0 + t + 4]);
            }
            #pragma unroll
            for (int mt = 0; mt < 2; mt++)
                #pragma unroll
                for (int nt = 0; nt < 4; nt++)
                    mma_tf32(acc[mt][nt], a[mt][0], a[mt][1], a[mt][2], a[mt][3],
                             b[nt][0], b[nt][1]);
        }
        __syncthreads();
    }

    // --- epilogue: phi for z<2; write (n,h,l,d); cols 2t,2t+1 -> float2
    #pragma unroll
    for (int mt = 0; mt < 2; mt++) {
        #pragma unroll
        for (int nt = 0; nt < 4; nt++) {
            const int j0 = colStart + wn * 32 + nt * 8 + 2 * t;
            const int h = j0 >> 5;
            const int d = j0 & 31;
            #pragma unroll
            for (int half = 0; half < 2; half++) {
                const int m = rowStart + wm * 32 + mt * 16 + g + half * 8;
                const int n = m >> 13;
                const int l = m & (L_SEQ - 1);
                float v0 = acc[mt][nt][half * 2 + 0];
                float v1 = acc[mt][nt][half * 2 + 1];
                if (z < 2) {
                    v0 = (v0 > 0.f) ? (v0 + 1.f) : expf(v0);
                    v1 = (v1 > 0.f) ? (v1 + 1.f) : expf(v1);
                }
                size_t off = (((size_t)(n * NH + h) * L_SEQ) + l) * PD + d;
                *reinterpret_cast<float2*>(&O[off]) = make_float2(v0, v1);
            }
        }
    }
}

// ---------------- Kernel 2: per-chunk local scan -----------------------------
__global__ __launch_bounds__(128) void scan_kernel() {
    const int nh = blockIdx.x;         // 0..15
    const int ch = blockIdx.y;         // 0..NCHUNK-1
    const int s = ch * CL;
    const int tid = threadIdx.x;

    __shared__ float spq[(CL + 1) * PD];
    __shared__ float spk[CL * PD];
    __shared__ float sv [CL * PD];
    __shared__ float sc [CL];
    __shared__ float scp[CL];

    const float* __restrict__ pq = g_pq + (size_t)nh * L_SEQ * PD;
    const float* __restrict__ pk = g_pk + (size_t)nh * L_SEQ * PD;
    const float* __restrict__ v  = g_v  + (size_t)nh * L_SEQ * PD;

    // pq rows [s-1, s+CL)
    for (int i = tid; i < (CL + 1) * PD; i += 128) {
        int l = s - 1 + (i >> 5);
        spq[i] = (l >= 0) ? pq[(size_t)l * PD + (i & 31)] : 0.f;
    }
    for (int i = tid; i < CL * PD; i += 128) {
        spk[i] = pk[(size_t)s * PD + i];
        sv[i]  = v [(size_t)s * PD + i];
    }
    __syncthreads();

    // per-position coefficients
    if (tid < CL) {
        float c = 0.f, cp = 0.f;
        #pragma unroll
        for (int d = 0; d < PD; d++) {
            float dq = spq[(tid + 1) * PD + d] - spq[tid * PD + d];
            c  += dq * sv[tid * PD + d];
            cp += dq;
        }
        sc[tid] = c;
        scp[tid] = cp;
    }
    __syncthreads();

    // serial local prefix scan: lanes 0..31 -> num, 32..63 -> den
    if (tid < 64) {
        const int d = tid & 31;
        const bool isden = tid >= 32;
        const float* coef = isden ? scp : sc;
        float* ob = (isden ? g_denloc : g_numloc) + (size_t)nh * L_SEQ * PD + (size_t)s * PD + d;
        float acc = 0.f;
        #pragma unroll 4
        for (int m = 0; m < CL; m++) {
            acc += coef[m] * spk[m * PD + d];
            ob[(size_t)m * PD] = acc;
        }
        g_tot[(nh * NCHUNK + ch) * 64 + tid] = acc;
    }
}

// ---------------- Kernel 3: carries (exclusive scan over chunks) -------------
__global__ __launch_bounds__(64) void carry_kernel() {
    const int nh = blockIdx.x;     // 0..15
    const int slot = threadIdx.x;  // 0..63
    float acc = 0.f;
    for (int ch = 0; ch < NCHUNK; ch++) {
        const int idx = (nh * NCHUNK + ch) * 64 + slot;
        g_carry[idx] = acc;
        acc += g_tot[idx];
    }
}

// ---------------- Kernel 4: finalize -----------------------------------------
__global__ __launch_bounds__(256) void final_kernel(float* __restrict__ out) {
    const size_t idx = (size_t)blockIdx.x * 256 + threadIdx.x;  // over nh,l,d
    const int d = (int)(idx & 31);
    const size_t rest = idx >> 5;
    const int l = (int)(rest & (L_SEQ - 1));
    const int nh = (int)(rest >> 13);
    const int ch = l / CL;

    const float cn = g_carry[(nh * NCHUNK + ch) * 64 + d];
    const float cd = g_carry[(nh * NCHUNK + ch) * 64 + 32 + d];
    const float num = g_numloc[idx] + cn;
    const float den = g_denloc[idx] + cd;

    const int n = nh >> 3;
    const int h = nh & 7;
    out[((size_t)n * L_SEQ + l) * DIM + h * PD + d] = num / den;
}

// ---------------- launch ------------------------------------------------------
extern "C" void kernel_launch(void* const* d_in, const int* in_sizes, int n_in,
                              void* d_out, int out_size) {
    const float* Y  = (const float*)d_in[0];
    const float* X  = (const float*)d_in[1];
    const float* Wq = (const float*)d_in[2];
    const float* Wk = (const float*)d_in[3];
    const float* Wv = (const float*)d_in[4];
    // d_in[5] = mask; always 1 (causal) per problem setup
    float* out = (float*)d_out;

    dim3 pg(M_ROWS / 128, DIM / 64, 3);
    proj_kernel<<<pg, 256>>>(Y, X, Wq, Wk, Wv);

    dim3 sg(NHB, NCHUNK);
    scan_kernel<<<sg, 128>>>();

    carry_kernel<<<NHB, 64>>>();

    final_kernel<<<(size_t)NHB * L_SEQ * PD / 256, 256>>>(out);
}